// round 11
// baseline (speedup 1.0000x reference)
#include <cuda_runtime.h>
#include <cuda_fp16.h>

#define HH 512
#define WW 512
#define CC 128
#define NPTS 524288
#define PLANE_ELEMS (CC * HH * WW)

#define TRANS_BLOCKS (2 * HH * (WW / 32))  // 16384
#define SETUP_BLOCKS (NPTS / 256)          // 2048

// Bins: 16 texels wide (x), 8 tall (y) -> 32 x 64 = 2048 bins, ~256 pts each.
#define NBIN 2048
#define CAP 384        // mean 256 + 8 sigma; spill path covers the rest
#define BINPAD 32      // one 128B L2 line per counter
#define SPILL_CAP 8192
#define SPILL_BLOCKS 64

// Window: 17 x 9 texels, all 128 channels, fp16 = 39168 B (< 48KB static smem)
#define WCOLS 17
#define WROWS 9
#define WIN_UINT4 ((WROWS * WCOLS * CC * 2) / 16)  // 2448

// Transposed fp16 planes [H][W][C] (channel-last).
__device__ __align__(16) __half g_uvT[PLANE_ELEMS];
__device__ __align__(16) __half g_stT[PLANE_ELEMS];
// Binned 32B records: {uvTexel, stBase, uvW01, uvW23} {stW01, stW23, pid, 0}
__device__ __align__(16) uint4 g_brec[NBIN * CAP * 2];
__device__ __align__(128) int g_cnt[NBIN * BINPAD];
__device__ __align__(128) int g_spillcnt[32];
__device__ __align__(16) uint4 g_sprec[SPILL_CAP * 2];

__device__ __forceinline__ unsigned packw2(float a, float b) {
    __half2 h = __floats2half2_rn(a, b);
    return *(unsigned*)&h;
}
__device__ __forceinline__ __half2 u2h(unsigned u) { return *(__half2*)&u; }

// ---------------------------------------------------------------------------
// Kernel 0: zero bin + spill counters (graph replays rerun the atomics).
// ---------------------------------------------------------------------------
__global__ void zero_kernel() {
    const int i = blockIdx.x * 256 + threadIdx.x;
    g_cnt[i] = 0;
    if (i == 0) g_spillcnt[0] = 0;
}

// ---------------------------------------------------------------------------
// Kernel 1 (fused): full transpose f32[C,H,W] -> f16[H,W,C] (both planes)
// + per-point setup with direct binning (padded cursors, spill-safe).
// ---------------------------------------------------------------------------
__global__ __launch_bounds__(256) void prep_kernel(
    const float* __restrict__ uv, const float* __restrict__ st,
    const float4* __restrict__ xs, const float* __restrict__ b) {
    const int bid = blockIdx.x;
    const int tid = threadIdx.x;

    if (bid < TRANS_BLOCKS) {
        __shared__ float tile[CC][33];
        const int plane = bid >> 13;
        const int rem = bid & 8191;
        const int y = rem >> 4;
        const int x0 = (rem & 15) * 32;
        const int tx = tid & 31;
        const int ty = tid >> 5;

        const float* src = plane ? st : uv;
        __half* dst = plane ? g_stT : g_uvT;

        #pragma unroll
        for (int i = 0; i < 16; i++) {
            const int c = ty + i * 8;
            tile[c][tx] = src[c * (HH * WW) + y * WW + x0 + tx];
        }
        __syncthreads();

        const int c2 = (tid & 63) * 2;
        const int xb = tid >> 6;
        #pragma unroll
        for (int i = 0; i < 8; i++) {
            const int xi = xb + i * 4;
            __half2 v = __floats2half2_rn(tile[c2][xi], tile[c2 + 1][xi]);
            *(__half2*)(dst + (size_t)(y * WW + x0 + xi) * CC + c2) = v;
        }
    } else {
        const int i = (bid - TRANS_BLOCKS) * 256 + tid;
        const float4 p = __ldcs(&xs[i]);

        const float ixu = __fdividef(p.x - b[0], b[4] - b[0]) * (WW - 1);
        const float iyu = __fdividef(p.y - b[1], b[5] - b[1]) * (HH - 1);
        const float ixs = __fdividef(p.z - b[2], b[6] - b[2]) * (WW - 1);
        const float iys = __fdividef(p.w - b[3], b[7] - b[3]) * (HH - 1);

        const int xu0 = min(max(__float2int_rd(ixu), 0), WW - 2);
        const int yu0 = min(max(__float2int_rd(iyu), 0), HH - 2);
        const int xs0 = min(max(__float2int_rd(ixs), 0), WW - 2);
        const int ys0 = min(max(__float2int_rd(iys), 0), HH - 2);

        const float wxu = ixu - (float)xu0, wyu = iyu - (float)yu0;
        const float wxs = ixs - (float)xs0, wys = iys - (float)ys0;

        uint4 r0, r1;
        r0.x = (unsigned)(yu0 * WW + xu0);          // uv texel index
        r0.y = (unsigned)((ys0 * WW + xs0) * CC);   // st base (halfs)
        r0.z = packw2((1.f - wxu) * (1.f - wyu), wxu * (1.f - wyu));
        r0.w = packw2((1.f - wxu) * wyu, wxu * wyu);
        r1.x = packw2((1.f - wxs) * (1.f - wys), wxs * (1.f - wys));
        r1.y = packw2((1.f - wxs) * wys, wxs * wys);
        r1.z = (unsigned)i;  // pid
        r1.w = 0;

        const int key = (yu0 >> 3) * 32 + (xu0 >> 4);  // 64 x 32 bins
        const int slot = atomicAdd(&g_cnt[key * BINPAD], 1);
        if (slot < CAP) {
            const int s = key * CAP + slot;
            g_brec[2 * s] = r0;
            g_brec[2 * s + 1] = r1;
        } else {
            const int s = atomicAdd(&g_spillcnt[0], 1);
            if (s < SPILL_CAP) {
                g_sprec[2 * s] = r0;
                g_sprec[2 * s + 1] = r1;
            }
        }
    }
}

// ---------------------------------------------------------------------------
// Point body: 16 lanes/point, lane gl = channels 8*gl..8*gl+7 (uint4/corner).
// uv corners from smem window (SMEM=true) or global (spill path).
// ---------------------------------------------------------------------------
template <bool SMEM>
__device__ __forceinline__ void process_point(
    const uint4 r0, const uint4 r1, int gl, const __half* __restrict__ win,
    int by, int bx, float* __restrict__ out) {
    const int t = (int)r0.x;
    const int y0 = t >> 9, x0 = t & 511;

    const __half* U;
    int dx, dy;
    if (SMEM) {
        const int ly = y0 - (by << 3);
        const int lx = x0 - (bx << 4);
        U = win + ((ly * WCOLS + lx) * CC + gl * 8);
        dx = CC;            // +1 texel in window
        dy = WCOLS * CC;    // +1 row in window
    } else {
        U = g_uvT + ((size_t)t * CC + gl * 8);
        dx = CC;
        dy = WW * CC;
    }
    const __half* S = g_stT + r0.y + gl * 8;

    const uint4 u00 = *(const uint4*)(U);
    const uint4 u01 = *(const uint4*)(U + dx);
    const uint4 u10 = *(const uint4*)(U + dy);
    const uint4 u11 = *(const uint4*)(U + dy + dx);
    const uint4 s00 = *(const uint4*)(S);
    const uint4 s01 = *(const uint4*)(S + CC);
    const uint4 s10 = *(const uint4*)(S + WW * CC);
    const uint4 s11 = *(const uint4*)(S + WW * CC + CC);

    __half2 au[4], av[4];
    {
        const __half2 wp = u2h(r0.z), wq = u2h(r0.w);
        const __half2 w00 = __low2half2(wp), w01 = __high2half2(wp);
        const __half2 w10 = __low2half2(wq), w11 = __high2half2(wq);
        const __half2* p00 = (const __half2*)&u00;
        const __half2* p01 = (const __half2*)&u01;
        const __half2* p10 = (const __half2*)&u10;
        const __half2* p11 = (const __half2*)&u11;
        #pragma unroll
        for (int j = 0; j < 4; j++) {
            __half2 a = __hmul2(p00[j], w00);
            a = __hfma2(p01[j], w01, a);
            a = __hfma2(p10[j], w10, a);
            au[j] = __hfma2(p11[j], w11, a);
        }
    }
    {
        const __half2 wp = u2h(r1.x), wq = u2h(r1.y);
        const __half2 w00 = __low2half2(wp), w01 = __high2half2(wp);
        const __half2 w10 = __low2half2(wq), w11 = __high2half2(wq);
        const __half2* p00 = (const __half2*)&s00;
        const __half2* p01 = (const __half2*)&s01;
        const __half2* p10 = (const __half2*)&s10;
        const __half2* p11 = (const __half2*)&s11;
        #pragma unroll
        for (int j = 0; j < 4; j++) {
            __half2 a = __hmul2(p00[j], w00);
            a = __hfma2(p01[j], w01, a);
            a = __hfma2(p10[j], w10, a);
            av[j] = __hfma2(p11[j], w11, a);
        }
    }

    // f[j] = partial for output j (channel 8*gl+j -> out j since 8*gl % 8 = 0).
    float f[8];
    #pragma unroll
    for (int j = 0; j < 4; j++) {
        const float2 tt = __half22float2(__hmul2(au[j], av[j]));
        f[2 * j] = tt.x;
        f[2 * j + 1] = tt.y;
    }

    // Sum across the 16 lanes (16 components).
    #pragma unroll
    for (int s = 8; s >= 1; s >>= 1) {
        #pragma unroll
        for (int j = 0; j < 8; j++)
            f[j] += __shfl_xor_sync(0xffffffffu, f[j], s);
    }

    if (gl == 0) {
        const int pid = (int)r1.z;
        float4 o0, o1;
        o0.x = 1.f / (1.f + __expf(-f[0]));
        o0.y = 1.f / (1.f + __expf(-f[1]));
        o0.z = 1.f / (1.f + __expf(-f[2]));
        o0.w = 1.f / (1.f + __expf(-f[3]));
        o1.x = 1.f / (1.f + __expf(-f[4]));
        o1.y = 1.f / (1.f + __expf(-f[5]));
        o1.z = 1.f / (1.f + __expf(-f[6]));
        o1.w = 1.f / (1.f + __expf(-f[7]));
        __stcs(&((float4*)out)[pid * 2], o0);
        __stcs(&((float4*)out)[pid * 2 + 1], o1);
    }
}

// ---------------------------------------------------------------------------
// Kernel 2: one block per bin. Load the bin's uv window into smem once,
// then process the bin's points (16 lanes/pt, record prefetch).
// Blocks past NBIN handle the spill list with global uv loads.
// ---------------------------------------------------------------------------
__global__ __launch_bounds__(256) void pass_kernel(float* __restrict__ out) {
    __shared__ __half win[WROWS * WCOLS * CC];
    const int tid = threadIdx.x;
    const int g = tid >> 4;
    const int gl = tid & 15;

    if (blockIdx.x < NBIN) {
        const int bin = blockIdx.x;
        const int by = bin >> 5;   // 0..63 (y bins of 8 rows)
        const int bx = bin & 31;   // 0..31 (x bins of 16 cols)
        const int n = min(g_cnt[bin * BINPAD], CAP);
        if (n == 0) return;

        // Load 17x9-texel window (all channels). __ldcs: read-once stream.
        for (int i = tid; i < WIN_UINT4; i += 256) {
            const int texel = i >> 4;       // 16 uint4 per texel
            const int chunk = i & 15;
            const int r = texel / WCOLS;
            const int c = texel - r * WCOLS;
            const int gy = min((by << 3) + r, HH - 1);
            const int gx = min((bx << 4) + c, WW - 1);
            ((uint4*)win)[i] =
                __ldcs((const uint4*)(g_uvT + (size_t)(gy * WW + gx) * CC) + chunk);
        }
        __syncthreads();

        // Process points with next-record prefetch.
        int i = g;
        uint4 r0, r1;
        if (i < n) {
            const int s = bin * CAP + i;
            r0 = __ldcs(&g_brec[2 * s]);
            r1 = __ldcs(&g_brec[2 * s + 1]);
        }
        while (i < n) {
            const int nx = i + 16;
            uint4 n0, n1;
            if (nx < n) {
                const int s = bin * CAP + nx;
                n0 = __ldcs(&g_brec[2 * s]);
                n1 = __ldcs(&g_brec[2 * s + 1]);
            }
            process_point<true>(r0, r1, gl, win, by, bx, out);
            r0 = n0; r1 = n1; i = nx;
        }
    } else {
        const int sb = blockIdx.x - NBIN;
        const int n = min(g_spillcnt[0], SPILL_CAP);
        for (int i = sb * 16 + g; i < n; i += SPILL_BLOCKS * 16) {
            const uint4 r0 = g_sprec[2 * i];
            const uint4 r1 = g_sprec[2 * i + 1];
            process_point<false>(r0, r1, gl, nullptr, 0, 0, out);
        }
    }
}

// ---------------------------------------------------------------------------
extern "C" void kernel_launch(void* const* d_in, const int* in_sizes, int n_in,
                              void* d_out, int out_size) {
    const float* x = (const float*)d_in[0];
    const float* uv = (const float*)d_in[1];
    const float* st = (const float*)d_in[2];
    const float* bounds = (const float*)d_in[3];
    float* out = (float*)d_out;

    zero_kernel<<<(NBIN * BINPAD) / 256, 256>>>();
    prep_kernel<<<TRANS_BLOCKS + SETUP_BLOCKS, 256>>>(
        uv, st, (const float4*)x, bounds);
    pass_kernel<<<NBIN + SPILL_BLOCKS, 256>>>(out);
}

// round 12
// speedup vs baseline: 1.2660x; 1.2660x over previous
#include <cuda_runtime.h>
#include <cuda_fp16.h>

#define HH 512
#define WW 512
#define CC 128
#define NPTS 524288
#define PLANE_ELEMS (CC * HH * WW)

#define THALF_BLOCKS (2 * HH * (WW / 32))  // 16384: half-channel transpose tiles
#define SETUP_BLOCKS (NPTS / 256)          // 2048
#define PASS_BLOCKS (NPTS / 32)            // 16384: 32 points/block, 8 lanes/pt

// Transposed fp16 planes [H][W][C] (channel-last).
__device__ __align__(16) __half g_uvT[PLANE_ELEMS];
__device__ __align__(16) __half g_stT[PLANE_ELEMS];
// 16B per-point record: {uvBase, stBase, h2(wxu,wyu), h2(wxs,wys)}
__device__ __align__(16) uint4 g_rec[NPTS];
// fp16 partials from pass A: 8 halfs per point (one uint4).
__device__ __align__(16) uint4 g_part[NPTS];

__device__ __forceinline__ unsigned packw2(float a, float b) {
    __half2 h = __floats2half2_rn(a, b);
    return *(unsigned*)&h;
}
__device__ __forceinline__ __half2 u2h(unsigned u) { return *(__half2*)&u; }

// ---------------------------------------------------------------------------
// Half-channel transpose tile: [C,H,W] f32 -> [H,W,C] f16 for 64 channels.
// STREAM=true uses evict-first hints (when fused with a pass that owns L2).
// ---------------------------------------------------------------------------
template <int CHOFF, bool STREAM>
__device__ __forceinline__ void transpose_half(
    int tbid, int tid, const float* __restrict__ uv,
    const float* __restrict__ st) {
    __shared__ float tile[64][33];
    const int plane = tbid >> 13;            // /8192
    const int rem = tbid & 8191;
    const int y = rem >> 4;
    const int x0 = (rem & 15) * 32;
    const int tx = tid & 31;
    const int ty = tid >> 5;  // 0..7

    const float* src = plane ? st : uv;
    __half* dst = plane ? g_stT : g_uvT;

    #pragma unroll
    for (int i = 0; i < 8; i++) {
        const int c = ty + i * 8;  // 0..63
        const float* sp = &src[(size_t)(CHOFF + c) * (HH * WW) + y * WW + x0 + tx];
        tile[c][tx] = STREAM ? __ldcs(sp) : *sp;
    }
    __syncthreads();

    const int c2 = (tid & 31) * 2;  // 0..62
    const int xb = tid >> 5;        // 0..7
    #pragma unroll
    for (int i = 0; i < 4; i++) {
        const int xi = xb + i * 8;
        __half2 v = __floats2half2_rn(tile[c2][xi], tile[c2 + 1][xi]);
        __half2* dp = (__half2*)(dst + (size_t)(y * WW + x0 + xi) * CC + CHOFF + c2);
        if (STREAM) __stcs((uint*)dp, *(uint*)&v);
        else *dp = v;
    }
}

// ---------------------------------------------------------------------------
// Per-point bilinear pass body: 8 lanes/point, lane gl = channels CHOFF+8*gl.
// Corner weights reconstructed in-register from packed (wx, wy).
// ---------------------------------------------------------------------------
template <int CHOFF, bool FIRST>
__device__ __forceinline__ void pass_body(int pbid, int tid,
                                          float* __restrict__ out) {
    const int p = pbid * 32 + (tid >> 3);
    const int gl = tid & 7;

    const uint4 r = __ldcs(&g_rec[p]);

    const __half* U = g_uvT + r.x + CHOFF + gl * 8;
    const __half* S = g_stT + r.y + CHOFF + gl * 8;

    const uint4 u00 = *(const uint4*)(U);
    const uint4 u01 = *(const uint4*)(U + CC);
    const uint4 u10 = *(const uint4*)(U + WW * CC);
    const uint4 u11 = *(const uint4*)(U + WW * CC + CC);
    const uint4 s00 = *(const uint4*)(S);
    const uint4 s01 = *(const uint4*)(S + CC);
    const uint4 s10 = *(const uint4*)(S + WW * CC);
    const uint4 s11 = *(const uint4*)(S + WW * CC + CC);

    const __half2 one = __float2half2_rn(1.f);

    __half2 au[4], av[4];
    {
        const __half2 h = u2h(r.z);  // (wxu, wyu)
        const __half2 wx = __low2half2(h), wy = __high2half2(h);
        const __half2 ix = __hsub2(one, wx), iy = __hsub2(one, wy);
        const __half2 w00 = __hmul2(ix, iy), w01 = __hmul2(wx, iy);
        const __half2 w10 = __hmul2(ix, wy), w11 = __hmul2(wx, wy);
        const __half2* p00 = (const __half2*)&u00;
        const __half2* p01 = (const __half2*)&u01;
        const __half2* p10 = (const __half2*)&u10;
        const __half2* p11 = (const __half2*)&u11;
        #pragma unroll
        for (int j = 0; j < 4; j++) {
            __half2 a = __hmul2(p00[j], w00);
            a = __hfma2(p01[j], w01, a);
            a = __hfma2(p10[j], w10, a);
            au[j] = __hfma2(p11[j], w11, a);
        }
    }
    {
        const __half2 h = u2h(r.w);  // (wxs, wys)
        const __half2 wx = __low2half2(h), wy = __high2half2(h);
        const __half2 ix = __hsub2(one, wx), iy = __hsub2(one, wy);
        const __half2 w00 = __hmul2(ix, iy), w01 = __hmul2(wx, iy);
        const __half2 w10 = __hmul2(ix, wy), w11 = __hmul2(wx, wy);
        const __half2* p00 = (const __half2*)&s00;
        const __half2* p01 = (const __half2*)&s01;
        const __half2* p10 = (const __half2*)&s10;
        const __half2* p11 = (const __half2*)&s11;
        #pragma unroll
        for (int j = 0; j < 4; j++) {
            __half2 a = __hmul2(p00[j], w00);
            a = __hfma2(p01[j], w01, a);
            a = __hfma2(p10[j], w10, a);
            av[j] = __hfma2(p11[j], w11, a);
        }
    }

    // Products -> f32; lane gl covers outs 0..7 for component CHOFF/8 + gl.
    float f[8];
    #pragma unroll
    for (int j = 0; j < 4; j++) {
        const float2 t = __half22float2(__hmul2(au[j], av[j]));
        f[2 * j] = t.x;
        f[2 * j + 1] = t.y;
    }

    // Sum the 8 components of this pass across the 8-lane group.
    #pragma unroll
    for (int s = 4; s >= 1; s >>= 1) {
        #pragma unroll
        for (int j = 0; j < 8; j++)
            f[j] += __shfl_xor_sync(0xffffffffu, f[j], s);
    }

    if (gl == 0) {
        if (FIRST) {
            uint4 pk;
            pk.x = packw2(f[0], f[1]);
            pk.y = packw2(f[2], f[3]);
            pk.z = packw2(f[4], f[5]);
            pk.w = packw2(f[6], f[7]);
            __stcs(&g_part[p], pk);
        } else {
            const uint4 pk = __ldcs(&g_part[p]);
            const float2 a0 = __half22float2(u2h(pk.x));
            const float2 a1 = __half22float2(u2h(pk.y));
            const float2 a2 = __half22float2(u2h(pk.z));
            const float2 a3 = __half22float2(u2h(pk.w));
            float4 o0, o1;
            o0.x = 1.f / (1.f + __expf(-(f[0] + a0.x)));
            o0.y = 1.f / (1.f + __expf(-(f[1] + a0.y)));
            o0.z = 1.f / (1.f + __expf(-(f[2] + a1.x)));
            o0.w = 1.f / (1.f + __expf(-(f[3] + a1.y)));
            o1.x = 1.f / (1.f + __expf(-(f[4] + a2.x)));
            o1.y = 1.f / (1.f + __expf(-(f[5] + a2.y)));
            o1.z = 1.f / (1.f + __expf(-(f[6] + a3.x)));
            o1.w = 1.f / (1.f + __expf(-(f[7] + a3.y)));
            __stcs(&((float4*)out)[p * 2], o0);
            __stcs(&((float4*)out)[p * 2 + 1], o1);
        }
    }
}

// ---------------------------------------------------------------------------
// K1: transpose ch 0-63 (both planes) + per-point setup (16B records).
// ---------------------------------------------------------------------------
__global__ __launch_bounds__(256) void k1_kernel(
    const float* __restrict__ uv, const float* __restrict__ st,
    const float4* __restrict__ xs, const float* __restrict__ b) {
    const int bid = blockIdx.x;
    const int tid = threadIdx.x;

    if (bid < THALF_BLOCKS) {
        transpose_half<0, false>(bid, tid, uv, st);
    } else {
        const int i = (bid - THALF_BLOCKS) * 256 + tid;
        const float4 p = __ldcs(&xs[i]);

        const float ixu = __fdividef(p.x - b[0], b[4] - b[0]) * (WW - 1);
        const float iyu = __fdividef(p.y - b[1], b[5] - b[1]) * (HH - 1);
        const float ixs = __fdividef(p.z - b[2], b[6] - b[2]) * (WW - 1);
        const float iys = __fdividef(p.w - b[3], b[7] - b[3]) * (HH - 1);

        const int xu0 = min(max(__float2int_rd(ixu), 0), WW - 2);
        const int yu0 = min(max(__float2int_rd(iyu), 0), HH - 2);
        const int xs0 = min(max(__float2int_rd(ixs), 0), WW - 2);
        const int ys0 = min(max(__float2int_rd(iys), 0), HH - 2);

        uint4 r;
        r.x = (unsigned)((yu0 * WW + xu0) * CC);
        r.y = (unsigned)((ys0 * WW + xs0) * CC);
        r.z = packw2(ixu - (float)xu0, iyu - (float)yu0);
        r.w = packw2(ixs - (float)xs0, iys - (float)ys0);
        g_rec[i] = r;
    }
}

// ---------------------------------------------------------------------------
// K2 (fused): passA (ch 0-63, LTS-bound) || transpose ch 64-127 (DRAM-bound).
// ---------------------------------------------------------------------------
__global__ __launch_bounds__(256) void k2_kernel(
    const float* __restrict__ uv, const float* __restrict__ st,
    float* __restrict__ out) {
    const int bid = blockIdx.x;
    const int tid = threadIdx.x;
    if (bid & 1) {
        transpose_half<64, true>(bid >> 1, tid, uv, st);
    } else {
        pass_body<0, true>(bid >> 1, tid, out);
    }
}

// ---------------------------------------------------------------------------
// K3: passB (ch 64-127) + combine + sigmoid + store.
// ---------------------------------------------------------------------------
__global__ __launch_bounds__(256) void k3_kernel(float* __restrict__ out) {
    pass_body<64, false>(blockIdx.x, threadIdx.x, out);
}

// ---------------------------------------------------------------------------
extern "C" void kernel_launch(void* const* d_in, const int* in_sizes, int n_in,
                              void* d_out, int out_size) {
    const float* x = (const float*)d_in[0];
    const float* uv = (const float*)d_in[1];
    const float* st = (const float*)d_in[2];
    const float* bounds = (const float*)d_in[3];
    float* out = (float*)d_out;

    k1_kernel<<<THALF_BLOCKS + SETUP_BLOCKS, 256>>>(
        uv, st, (const float4*)x, bounds);
    k2_kernel<<<THALF_BLOCKS + PASS_BLOCKS, 256>>>(uv, st, out);
    k3_kernel<<<PASS_BLOCKS, 256>>>(out);
}